// round 2
// baseline (speedup 1.0000x reference)
#include <cuda_runtime.h>
#include <cuda_bf16.h>
#include <cstdint>

#define N_NODES 50000
#define N_EDGES 800000
#define N_GRAPHS 128

// ---------------- scratch (device globals; no allocations allowed) ----------------
__device__ float g_z1[N_NODES * 96];
__device__ float g_x1[N_NODES * 96];
__device__ float g_z2[N_NODES * 192];
__device__ float g_x2[N_NODES * 192];
__device__ float g_el1[N_NODES * 3];
__device__ float g_er1[N_NODES * 3];
__device__ float g_el2[N_NODES * 3];
__device__ float g_er2[N_NODES * 3];
__device__ int   g_deg[N_NODES];
__device__ int   g_off[N_NODES + 1];
__device__ int   g_cursor[N_NODES];
__device__ int   g_btot[64];
__device__ int   g_boff[64];
__device__ int   g_ssrc[N_EDGES];
__device__ float g_pool[N_GRAPHS * 192];

// ---------------- CSR build ----------------
__global__ void zero_kernel() {
    int i = blockIdx.x * blockDim.x + threadIdx.x;
    if (i < N_NODES) g_deg[i] = 0;
    if (i < N_GRAPHS * 192) g_pool[i] = 0.f;
}

__global__ void hist_kernel(const int* __restrict__ dst) {
    int e = blockIdx.x * blockDim.x + threadIdx.x;
    if (e < N_EDGES) atomicAdd(&g_deg[__ldg(dst + e)], 1);
}

__global__ void scan1_kernel() {
    __shared__ int sm[1024];
    int t = threadIdx.x;
    int i = blockIdx.x * 1024 + t;
    int v = (i < N_NODES) ? g_deg[i] : 0;
    sm[t] = v;
    __syncthreads();
#pragma unroll
    for (int o = 1; o < 1024; o <<= 1) {
        int x = (t >= o) ? sm[t - o] : 0;
        __syncthreads();
        sm[t] += x;
        __syncthreads();
    }
    if (i < N_NODES) g_off[i] = sm[t] - v;          // exclusive (block-local)
    if (t == 1023) g_btot[blockIdx.x] = sm[1023];   // block total
}

__global__ void scan2_kernel(int nb) {
    __shared__ int sm[64];
    int t = threadIdx.x;
    int v = (t < nb) ? g_btot[t] : 0;
    sm[t] = v;
    __syncthreads();
#pragma unroll
    for (int o = 1; o < 64; o <<= 1) {
        int x = (t >= o) ? sm[t - o] : 0;
        __syncthreads();
        sm[t] += x;
        __syncthreads();
    }
    if (t < nb) g_boff[t] = sm[t] - v;
}

__global__ void scan3_kernel() {
    int i = blockIdx.x * blockDim.x + threadIdx.x;
    if (i < N_NODES) {
        int v = g_off[i] + g_boff[i >> 10];
        g_off[i] = v;
        g_cursor[i] = v;
    }
    if (i == 0) g_off[N_NODES] = N_EDGES;
}

__global__ void scatter_kernel(const int* __restrict__ src, const int* __restrict__ dst) {
    int e = blockIdx.x * blockDim.x + threadIdx.x;
    if (e < N_EDGES) {
        int d = __ldg(dst + e);
        int p = atomicAdd(&g_cursor[d], 1);
        g_ssrc[p] = __ldg(src + e);
    }
}

// ---------------- layer 1: z1 = feature @ W1 ; el1/er1 ----------------
__global__ void k1_kernel(const float* __restrict__ feat, const float* __restrict__ W1,
                          const float* __restrict__ al, const float* __restrict__ ar) {
    int warp = (blockIdx.x * blockDim.x + threadIdx.x) >> 5;
    if (warp >= N_NODES) return;
    int lane = threadIdx.x & 31;
    float f[10];
#pragma unroll
    for (int k = 0; k < 10; k++) f[k] = __ldg(feat + warp * 10 + k);
    float el[3], er[3];
#pragma unroll
    for (int h = 0; h < 3; h++) {
        int c = h * 32 + lane;
        float z = 0.f;
#pragma unroll
        for (int k = 0; k < 10; k++) z += f[k] * __ldg(W1 + k * 96 + c);
        g_z1[warp * 96 + c] = z;
        el[h] = z * __ldg(al + c);
        er[h] = z * __ldg(ar + c);
    }
#pragma unroll
    for (int o = 16; o; o >>= 1) {
#pragma unroll
        for (int h = 0; h < 3; h++) {
            el[h] += __shfl_xor_sync(0xffffffffu, el[h], o);
            er[h] += __shfl_xor_sync(0xffffffffu, er[h], o);
        }
    }
    if (lane == 0) {
#pragma unroll
        for (int h = 0; h < 3; h++) {
            g_el1[warp * 3 + h] = el[h];
            g_er1[warp * 3 + h] = er[h];
        }
    }
}

// ---------------- GAT aggregation: warp per dst node, online softmax ----------------
// NOTE: buffers are bound inside device code (passing __device__ globals as
// kernel args from host code passes the host shadow address -> fault).
template <int D>
__device__ __forceinline__ void agg_body(const float* __restrict__ z,
                                         const float* __restrict__ el,
                                         const float* __restrict__ er,
                                         float* __restrict__ xout) {
    int node = (blockIdx.x * blockDim.x + threadIdx.x) >> 5;
    if (node >= N_NODES) return;
    int lane = threadIdx.x & 31;
    constexpr int C = D / 32;
    float acc[3][C];
    float m[3], s[3], erd[3];
#pragma unroll
    for (int h = 0; h < 3; h++) {
        m[h] = -1e30f;
        s[h] = 0.f;
        erd[h] = __ldg(er + node * 3 + h);
#pragma unroll
        for (int c = 0; c < C; c++) acc[h][c] = 0.f;
    }
    int beg = g_off[node], end = g_off[node + 1];
    for (int i = beg; i < end; i++) {
        int sn = g_ssrc[i];
        const float* zp = z + (size_t)sn * (3 * D);
#pragma unroll
        for (int h = 0; h < 3; h++) {
            float e = __ldg(el + sn * 3 + h) + erd[h];
            e = e > 0.f ? e : 0.2f * e;   // leaky relu
            float w;
            if (e > m[h]) {
                float r = __expf(m[h] - e);
                s[h] *= r;
#pragma unroll
                for (int c = 0; c < C; c++) acc[h][c] *= r;
                m[h] = e;
                w = 1.f;
            } else {
                w = __expf(e - m[h]);
            }
            s[h] += w;
#pragma unroll
            for (int c = 0; c < C; c++)
                acc[h][c] += w * __ldg(zp + h * D + c * 32 + lane);
        }
    }
    float* xo = xout + (size_t)node * (3 * D);
#pragma unroll
    for (int h = 0; h < 3; h++) {
        float inv = 1.f / (s[h] + 1e-16f);
#pragma unroll
        for (int c = 0; c < C; c++) {
            float v = acc[h][c] * inv;
            xo[h * D + c * 32 + lane] = v > 0.f ? v : 0.f;   // relu
        }
    }
}

__global__ void agg1_kernel() { agg_body<32>(g_z1, g_el1, g_er1, g_x1); }
__global__ void agg2_kernel() { agg_body<64>(g_z2, g_el2, g_er2, g_x2); }

// ---------------- layer 2 GEMM: z2[N,192] = x1[N,96] @ W2[96,192] ----------------
__global__ __launch_bounds__(256) void gemm2_kernel(const float* __restrict__ W2) {
    __shared__ float xs[32][65];     // transposed x tile, padded
    __shared__ float ws[32][192];
    int tid = threadIdx.x;
    int tx = tid & 15, ty = tid >> 4;
    int n0 = blockIdx.x * 64;
    float acc[4][12];
#pragma unroll
    for (int i = 0; i < 4; i++)
#pragma unroll
        for (int j = 0; j < 12; j++) acc[i][j] = 0.f;

    for (int kt = 0; kt < 3; kt++) {
#pragma unroll
        for (int r = 0; r < 8; r++) {
            int idx = r * 256 + tid;
            int m = idx >> 5, k = idx & 31;
            int node = n0 + m;
            xs[k][m] = (node < N_NODES) ? g_x1[(size_t)node * 96 + kt * 32 + k] : 0.f;
        }
#pragma unroll
        for (int r = 0; r < 24; r++) {
            int idx = r * 256 + tid;
            int k = idx / 192, c = idx % 192;
            ws[k][c] = __ldg(W2 + (kt * 32 + k) * 192 + c);
        }
        __syncthreads();
#pragma unroll
        for (int k = 0; k < 32; k++) {
            float a[4], b[12];
#pragma unroll
            for (int i = 0; i < 4; i++) a[i] = xs[k][ty * 4 + i];
#pragma unroll
            for (int j = 0; j < 12; j++) b[j] = ws[k][tx * 12 + j];
#pragma unroll
            for (int i = 0; i < 4; i++)
#pragma unroll
                for (int j = 0; j < 12; j++) acc[i][j] += a[i] * b[j];
        }
        __syncthreads();
    }
#pragma unroll
    for (int i = 0; i < 4; i++) {
        int node = n0 + ty * 4 + i;
        if (node < N_NODES) {
#pragma unroll
            for (int j = 0; j < 12; j++)
                g_z2[(size_t)node * 192 + tx * 12 + j] = acc[i][j];
        }
    }
}

// ---------------- el2/er2 from z2 ----------------
__global__ void elr2_kernel(const float* __restrict__ al, const float* __restrict__ ar) {
    int warp = (blockIdx.x * blockDim.x + threadIdx.x) >> 5;
    if (warp >= N_NODES) return;
    int lane = threadIdx.x & 31;
    const float* zp = g_z2 + (size_t)warp * 192;
    float el[3], er[3];
#pragma unroll
    for (int h = 0; h < 3; h++) {
        float z0 = zp[h * 64 + lane];
        float z1 = zp[h * 64 + 32 + lane];
        el[h] = z0 * __ldg(al + h * 64 + lane) + z1 * __ldg(al + h * 64 + 32 + lane);
        er[h] = z0 * __ldg(ar + h * 64 + lane) + z1 * __ldg(ar + h * 64 + 32 + lane);
    }
#pragma unroll
    for (int o = 16; o; o >>= 1) {
#pragma unroll
        for (int h = 0; h < 3; h++) {
            el[h] += __shfl_xor_sync(0xffffffffu, el[h], o);
            er[h] += __shfl_xor_sync(0xffffffffu, er[h], o);
        }
    }
    if (lane == 0) {
#pragma unroll
        for (int h = 0; h < 3; h++) {
            g_el2[warp * 3 + h] = el[h];
            g_er2[warp * 3 + h] = er[h];
        }
    }
}

// ---------------- pooling: graph_ids sorted -> run-length local sums ----------------
__global__ void pool_kernel(const int* __restrict__ gid) {
    int c = threadIdx.x;   // 192 threads
    int n0 = blockIdx.x * 256;
    int nend = n0 + 256;
    if (nend > N_NODES) nend = N_NODES;
    if (n0 >= N_NODES) return;
    int curg = __ldg(gid + n0);
    float a = 0.f;
    for (int n = n0; n < nend; n++) {
        int g = __ldg(gid + n);
        if (g != curg) {
            atomicAdd(&g_pool[curg * 192 + c], a);
            a = 0.f;
            curg = g;
        }
        a += g_x2[(size_t)n * 192 + c];
    }
    atomicAdd(&g_pool[curg * 192 + c], a);
}

// ---------------- MLP head: one block per graph ----------------
__global__ void mlp_kernel(const int* __restrict__ gid, const float* __restrict__ d1w,
                           const float* __restrict__ d1b, const float* __restrict__ d2w,
                           const float* __restrict__ d2b, float* __restrict__ out) {
    int g = blockIdx.x;
    int t = threadIdx.x;   // 64
    __shared__ float red[2];
    __shared__ float s_inv;
    if (t == 0) {
        // lower_bound(g), lower_bound(g+1) on sorted gid
        int lo = 0, hi = N_NODES;
        while (lo < hi) { int mid = (lo + hi) >> 1; if (__ldg(gid + mid) < g) lo = mid + 1; else hi = mid; }
        int lb = lo;
        lo = 0; hi = N_NODES;
        while (lo < hi) { int mid = (lo + hi) >> 1; if (__ldg(gid + mid) < g + 1) lo = mid + 1; else hi = mid; }
        float cnt = (float)(lo - lb);
        s_inv = 1.f / fmaxf(cnt, 1.f);
    }
    __syncthreads();
    float inv = s_inv;
    float dot = 0.f;
#pragma unroll 4
    for (int k = 0; k < 192; k++)
        dot += g_pool[g * 192 + k] * __ldg(d1w + k * 64 + t);
    float h = __ldg(d1b + t) + inv * dot;
    h = fmaxf(h, 0.f);
    float v = h * __ldg(d2w + t);
#pragma unroll
    for (int o = 16; o; o >>= 1) v += __shfl_xor_sync(0xffffffffu, v, o);
    if ((t & 31) == 0) red[t >> 5] = v;
    __syncthreads();
    if (t == 0) out[g] = red[0] + red[1] + __ldg(d2b);
}

// ---------------- launch ----------------
extern "C" void kernel_launch(void* const* d_in, const int* in_sizes, int n_in,
                              void* d_out, int out_size) {
    const float* feature = (const float*)d_in[0];
    const int*   src     = (const int*)d_in[1];
    const int*   dst     = (const int*)d_in[2];
    const int*   gid     = (const int*)d_in[3];
    const float* W1      = (const float*)d_in[4];
    const float* al1     = (const float*)d_in[5];
    const float* ar1     = (const float*)d_in[6];
    const float* W2      = (const float*)d_in[7];
    const float* al2     = (const float*)d_in[8];
    const float* ar2     = (const float*)d_in[9];
    const float* d1w     = (const float*)d_in[10];
    const float* d1b     = (const float*)d_in[11];
    const float* d2w     = (const float*)d_in[12];
    const float* d2b     = (const float*)d_in[13];
    float* out = (float*)d_out;

    const int NB_SCAN = (N_NODES + 1023) / 1024;           // 49
    const int EB = (N_EDGES + 255) / 256;                  // 3125
    const int NBZ = (N_NODES + 255) / 256;                 // 196
    const int WARPB = (N_NODES * 32 + 255) / 256;          // 6250 (warp per node, 8 warps/block)
    const int GEMMB = (N_NODES + 63) / 64;                 // 782

    zero_kernel<<<NBZ, 256>>>();
    hist_kernel<<<EB, 256>>>(dst);
    scan1_kernel<<<NB_SCAN, 1024>>>();
    scan2_kernel<<<1, 64>>>(NB_SCAN);
    scan3_kernel<<<NBZ, 256>>>();
    scatter_kernel<<<EB, 256>>>(src, dst);

    k1_kernel<<<WARPB, 256>>>(feature, W1, al1, ar1);
    agg1_kernel<<<WARPB, 256>>>();

    gemm2_kernel<<<GEMMB, 256>>>(W2);
    elr2_kernel<<<WARPB, 256>>>(al2, ar2);
    agg2_kernel<<<WARPB, 256>>>();

    pool_kernel<<<NBZ, 192>>>(gid);
    mlp_kernel<<<N_GRAPHS, 64>>>(gid, d1w, d1b, d2w, d2b, out);
}

// round 8
// speedup vs baseline: 1.1687x; 1.1687x over previous
#include <cuda_runtime.h>
#include <cuda_bf16.h>
#include <cstdint>

#define N_NODES 50000
#define N_EDGES 800000
#define N_GRAPHS 128

// ---------------- scratch (device globals; no allocations allowed) ----------------
__device__ float g_z1[N_NODES * 96];
__device__ float g_x1[N_NODES * 96];
__device__ float g_z2[N_NODES * 192];
__device__ float g_x2[N_NODES * 192];
__device__ float g_el1[N_NODES * 3];
__device__ float g_er1[N_NODES * 3];
__device__ float g_el2[N_NODES * 3];
__device__ float g_er2[N_NODES * 3];
__device__ float g_s1[N_NODES * 3];
__device__ float g_s2[N_NODES * 3];
__device__ int   g_deg[N_NODES];
__device__ int   g_off[N_NODES + 1];
__device__ int   g_cursor[N_NODES];
__device__ int   g_btot[64];
__device__ int   g_boff[64];
__device__ int   g_ssrc[N_EDGES];
__device__ int   g_sdst[N_EDGES];
__device__ float g_w[N_EDGES * 3];
__device__ float g_pool[N_GRAPHS * 192];

// ---------------- init ----------------
__global__ void zero_kernel() {
    int i = blockIdx.x * blockDim.x + threadIdx.x;
    if (i < N_NODES) g_deg[i] = 0;
    if (i < N_GRAPHS * 192) g_pool[i] = 0.f;
    if (i < N_NODES * 3) {
        g_s1[i] = 0.f;
        g_s2[i] = 0.f;
    }
}

// ---------------- CSR build ----------------
__global__ void hist_kernel(const int* __restrict__ dst) {
    int e = blockIdx.x * blockDim.x + threadIdx.x;
    if (e < N_EDGES) atomicAdd(&g_deg[__ldg(dst + e)], 1);
}

__global__ void scan1_kernel() {
    __shared__ int sm[1024];
    int t = threadIdx.x;
    int i = blockIdx.x * 1024 + t;
    int v = (i < N_NODES) ? g_deg[i] : 0;
    sm[t] = v;
    __syncthreads();
#pragma unroll
    for (int o = 1; o < 1024; o <<= 1) {
        int x = (t >= o) ? sm[t - o] : 0;
        __syncthreads();
        sm[t] += x;
        __syncthreads();
    }
    if (i < N_NODES) g_off[i] = sm[t] - v;
    if (t == 1023) g_btot[blockIdx.x] = sm[1023];
}

__global__ void scan2_kernel(int nb) {
    __shared__ int sm[64];
    int t = threadIdx.x;
    int v = (t < nb) ? g_btot[t] : 0;
    sm[t] = v;
    __syncthreads();
#pragma unroll
    for (int o = 1; o < 64; o <<= 1) {
        int x = (t >= o) ? sm[t - o] : 0;
        __syncthreads();
        sm[t] += x;
        __syncthreads();
    }
    if (t < nb) g_boff[t] = sm[t] - v;
}

__global__ void scan3_kernel() {
    int i = blockIdx.x * blockDim.x + threadIdx.x;
    if (i < N_NODES) {
        int v = g_off[i] + g_boff[i >> 10];
        g_off[i] = v;
        g_cursor[i] = v;
    }
    if (i == 0) g_off[N_NODES] = N_EDGES;
}

__global__ void scatter_kernel(const int* __restrict__ src, const int* __restrict__ dst) {
    int e = blockIdx.x * blockDim.x + threadIdx.x;
    if (e < N_EDGES) {
        int d = __ldg(dst + e);
        int p = atomicAdd(&g_cursor[d], 1);
        g_ssrc[p] = __ldg(src + e);
        g_sdst[p] = d;
    }
}

// ---------------- layer 1: z1 = feature @ W1 ; el1/er1 ----------------
__global__ void k1_kernel(const float* __restrict__ feat, const float* __restrict__ W1,
                          const float* __restrict__ al, const float* __restrict__ ar) {
    int warp = (blockIdx.x * blockDim.x + threadIdx.x) >> 5;
    if (warp >= N_NODES) return;
    int lane = threadIdx.x & 31;
    float f[10];
#pragma unroll
    for (int k = 0; k < 10; k++) f[k] = __ldg(feat + warp * 10 + k);
    float el[3], er[3];
#pragma unroll
    for (int h = 0; h < 3; h++) {
        int c = h * 32 + lane;
        float z = 0.f;
#pragma unroll
        for (int k = 0; k < 10; k++) z += f[k] * __ldg(W1 + k * 96 + c);
        g_z1[warp * 96 + c] = z;
        el[h] = z * __ldg(al + c);
        er[h] = z * __ldg(ar + c);
    }
#pragma unroll
    for (int o = 16; o; o >>= 1) {
#pragma unroll
        for (int h = 0; h < 3; h++) {
            el[h] += __shfl_xor_sync(0xffffffffu, el[h], o);
            er[h] += __shfl_xor_sync(0xffffffffu, er[h], o);
        }
    }
    if (lane == 0) {
#pragma unroll
        for (int h = 0; h < 3; h++) {
            g_el1[warp * 3 + h] = el[h];
            g_er1[warp * 3 + h] = er[h];
        }
    }
}

// ---------------- softmax weights: w = exp(leakyrelu(el+er)) in CSR order ----------
// Softmax is shift-invariant; logits here are O(10) max, far from expf overflow,
// so the reference's max-subtraction can be dropped (identical result in fp32).
__global__ void ws1_kernel() {
    int p = blockIdx.x * blockDim.x + threadIdx.x;
    if (p >= N_EDGES) return;
    int sn = g_ssrc[p], d = g_sdst[p];
#pragma unroll
    for (int h = 0; h < 3; h++) {
        float v = g_el1[sn * 3 + h] + g_er1[d * 3 + h];
        v = v > 0.f ? v : 0.2f * v;
        float w = __expf(v);
        g_w[p * 3 + h] = w;
        atomicAdd(&g_s1[d * 3 + h], w);
    }
}

__global__ void ws2_kernel() {
    int p = blockIdx.x * blockDim.x + threadIdx.x;
    if (p >= N_EDGES) return;
    int sn = g_ssrc[p], d = g_sdst[p];
#pragma unroll
    for (int h = 0; h < 3; h++) {
        float v = g_el2[sn * 3 + h] + g_er2[d * 3 + h];
        v = v > 0.f ? v : 0.2f * v;
        float w = __expf(v);
        g_w[p * 3 + h] = w;
        atomicAdd(&g_s2[d * 3 + h], w);
    }
}

// ---------------- aggregation: warp per dst node, branch-free weighted gather ------
__global__ void agg1_kernel() {
    int node = (blockIdx.x * blockDim.x + threadIdx.x) >> 5;
    if (node >= N_NODES) return;
    int lane = threadIdx.x & 31;
    bool act = lane < 24;                 // 24 float4 = 96 floats
    int q = act ? lane : 23;
    int h = q >> 3;                       // head = float4 idx / 8
    float4 a = make_float4(0.f, 0.f, 0.f, 0.f);
    int beg = g_off[node], end = g_off[node + 1];
    const float4* z4 = (const float4*)g_z1;
    for (int p = beg; p < end; p++) {
        int sn = g_ssrc[p];
        float w = __ldg(&g_w[p * 3 + h]);
        w = act ? w : 0.f;
        float4 v = __ldg(&z4[(size_t)sn * 24 + q]);
        a.x += w * v.x; a.y += w * v.y; a.z += w * v.z; a.w += w * v.w;
    }
    if (act) {
        float inv = 1.f / (g_s1[node * 3 + h] + 1e-16f);
        float4 r;
        r.x = fmaxf(a.x * inv, 0.f); r.y = fmaxf(a.y * inv, 0.f);
        r.z = fmaxf(a.z * inv, 0.f); r.w = fmaxf(a.w * inv, 0.f);
        ((float4*)g_x1)[(size_t)node * 24 + q] = r;
    }
}

__global__ void agg2_kernel() {
    int node = (blockIdx.x * blockDim.x + threadIdx.x) >> 5;
    if (node >= N_NODES) return;
    int lane = threadIdx.x & 31;
    int h0 = lane >> 4;                   // head for first float4 (0 or 1)
    int q1 = 32 + (lane & 15);            // second float4 index (head 2)
    float4 a0 = make_float4(0.f, 0.f, 0.f, 0.f);
    float4 a1 = make_float4(0.f, 0.f, 0.f, 0.f);
    int beg = g_off[node], end = g_off[node + 1];
    const float4* z4 = (const float4*)g_z2;
    for (int p = beg; p < end; p++) {
        int sn = g_ssrc[p];
        float w0 = __ldg(&g_w[p * 3 + h0]);
        float w2 = __ldg(&g_w[p * 3 + 2]);
        w2 = (lane < 16) ? w2 : 0.f;
        const float4* zp = z4 + (size_t)sn * 48;
        float4 v0 = __ldg(zp + lane);
        float4 v1 = __ldg(zp + q1);
        a0.x += w0 * v0.x; a0.y += w0 * v0.y; a0.z += w0 * v0.z; a0.w += w0 * v0.w;
        a1.x += w2 * v1.x; a1.y += w2 * v1.y; a1.z += w2 * v1.z; a1.w += w2 * v1.w;
    }
    float inv0 = 1.f / (g_s2[node * 3 + h0] + 1e-16f);
    float inv2 = 1.f / (g_s2[node * 3 + 2] + 1e-16f);
    float4* xo = (float4*)g_x2 + (size_t)node * 48;
    float4 r0;
    r0.x = fmaxf(a0.x * inv0, 0.f); r0.y = fmaxf(a0.y * inv0, 0.f);
    r0.z = fmaxf(a0.z * inv0, 0.f); r0.w = fmaxf(a0.w * inv0, 0.f);
    xo[lane] = r0;
    if (lane < 16) {
        float4 r1;
        r1.x = fmaxf(a1.x * inv2, 0.f); r1.y = fmaxf(a1.y * inv2, 0.f);
        r1.z = fmaxf(a1.z * inv2, 0.f); r1.w = fmaxf(a1.w * inv2, 0.f);
        xo[q1] = r1;
    }
}

// ---------------- layer 2 GEMM + fused el2/er2 epilogue ----------------
__global__ __launch_bounds__(256) void gemm2_kernel(const float* __restrict__ W2,
                                                    const float* __restrict__ al2,
                                                    const float* __restrict__ ar2) {
    __shared__ float xs[32][65];
    __shared__ float ws[32][192];
    int tid = threadIdx.x;
    int tx = tid & 15, ty = tid >> 4;
    int n0 = blockIdx.x * 64;
    float acc[4][12];
#pragma unroll
    for (int i = 0; i < 4; i++)
#pragma unroll
        for (int j = 0; j < 12; j++) acc[i][j] = 0.f;

    for (int kt = 0; kt < 3; kt++) {
#pragma unroll
        for (int r = 0; r < 8; r++) {
            int idx = r * 256 + tid;
            int m = idx >> 5, k = idx & 31;
            int node = n0 + m;
            xs[k][m] = (node < N_NODES) ? g_x1[(size_t)node * 96 + kt * 32 + k] : 0.f;
        }
#pragma unroll
        for (int r = 0; r < 24; r++) {
            int idx = r * 256 + tid;
            int k = idx / 192, c = idx % 192;
            ws[k][c] = __ldg(W2 + (kt * 32 + k) * 192 + c);
        }
        __syncthreads();
#pragma unroll
        for (int k = 0; k < 32; k++) {
            float a[4], b[12];
#pragma unroll
            for (int i = 0; i < 4; i++) a[i] = xs[k][ty * 4 + i];
#pragma unroll
            for (int j = 0; j < 12; j++) b[j] = ws[k][tx * 12 + j];
#pragma unroll
            for (int i = 0; i < 4; i++)
#pragma unroll
                for (int j = 0; j < 12; j++) acc[i][j] += a[i] * b[j];
        }
        __syncthreads();
    }
#pragma unroll
    for (int i = 0; i < 4; i++) {
        int node = n0 + ty * 4 + i;
        if (node < N_NODES) {
#pragma unroll
            for (int j = 0; j < 12; j++)
                g_z2[(size_t)node * 192 + tx * 12 + j] = acc[i][j];
        }
        // fused el2/er2: per-thread partials over 12 cols, 16-lane shfl reduce
        float elp[3] = {0.f, 0.f, 0.f}, erp[3] = {0.f, 0.f, 0.f};
#pragma unroll
        for (int j = 0; j < 12; j++) {
            int col = tx * 12 + j;
            int h = col >> 6;
            float v = acc[i][j];
            elp[h] += v * __ldg(al2 + col);
            erp[h] += v * __ldg(ar2 + col);
        }
#pragma unroll
        for (int o = 1; o < 16; o <<= 1) {
#pragma unroll
            for (int h = 0; h < 3; h++) {
                elp[h] += __shfl_xor_sync(0xffffffffu, elp[h], o);
                erp[h] += __shfl_xor_sync(0xffffffffu, erp[h], o);
            }
        }
        if (tx == 0 && node < N_NODES) {
#pragma unroll
            for (int h = 0; h < 3; h++) {
                g_el2[node * 3 + h] = elp[h];
                g_er2[node * 3 + h] = erp[h];
            }
        }
    }
}

// ---------------- pooling: graph_ids sorted -> run-length local sums ----------------
__global__ void pool_kernel(const int* __restrict__ gid) {
    int c = threadIdx.x;   // 192 threads
    int n0 = blockIdx.x * 256;
    int nend = n0 + 256;
    if (nend > N_NODES) nend = N_NODES;
    if (n0 >= N_NODES) return;
    int curg = __ldg(gid + n0);
    float a = 0.f;
    for (int n = n0; n < nend; n++) {
        int g = __ldg(gid + n);
        if (g != curg) {
            atomicAdd(&g_pool[curg * 192 + c], a);
            a = 0.f;
            curg = g;
        }
        a += g_x2[(size_t)n * 192 + c];
    }
    atomicAdd(&g_pool[curg * 192 + c], a);
}

// ---------------- MLP head: one block per graph ----------------
__global__ void mlp_kernel(const int* __restrict__ gid, const float* __restrict__ d1w,
                           const float* __restrict__ d1b, const float* __restrict__ d2w,
                           const float* __restrict__ d2b, float* __restrict__ out) {
    int g = blockIdx.x;
    int t = threadIdx.x;   // 64
    __shared__ float red[2];
    __shared__ float s_inv;
    if (t == 0) {
        int lo = 0, hi = N_NODES;
        while (lo < hi) { int mid = (lo + hi) >> 1; if (__ldg(gid + mid) < g) lo = mid + 1; else hi = mid; }
        int lb = lo;
        lo = 0; hi = N_NODES;
        while (lo < hi) { int mid = (lo + hi) >> 1; if (__ldg(gid + mid) < g + 1) lo = mid + 1; else hi = mid; }
        float cnt = (float)(lo - lb);
        s_inv = 1.f / fmaxf(cnt, 1.f);
    }
    __syncthreads();
    float inv = s_inv;
    float dot = 0.f;
#pragma unroll 4
    for (int k = 0; k < 192; k++)
        dot += g_pool[g * 192 + k] * __ldg(d1w + k * 64 + t);
    float h = __ldg(d1b + t) + inv * dot;
    h = fmaxf(h, 0.f);
    float v = h * __ldg(d2w + t);
#pragma unroll
    for (int o = 16; o; o >>= 1) v += __shfl_xor_sync(0xffffffffu, v, o);
    if ((t & 31) == 0) red[t >> 5] = v;
    __syncthreads();
    if (t == 0) out[g] = red[0] + red[1] + __ldg(d2b);
}

// ---------------- launch ----------------
extern "C" void kernel_launch(void* const* d_in, const int* in_sizes, int n_in,
                              void* d_out, int out_size) {
    const float* feature = (const float*)d_in[0];
    const int*   src     = (const int*)d_in[1];
    const int*   dst     = (const int*)d_in[2];
    const int*   gid     = (const int*)d_in[3];
    const float* W1      = (const float*)d_in[4];
    const float* al1     = (const float*)d_in[5];
    const float* ar1     = (const float*)d_in[6];
    const float* W2      = (const float*)d_in[7];
    const float* al2     = (const float*)d_in[8];
    const float* ar2     = (const float*)d_in[9];
    const float* d1w     = (const float*)d_in[10];
    const float* d1b     = (const float*)d_in[11];
    const float* d2w     = (const float*)d_in[12];
    const float* d2b     = (const float*)d_in[13];
    float* out = (float*)d_out;

    const int NB_SCAN = (N_NODES + 1023) / 1024;           // 49
    const int EB = (N_EDGES + 255) / 256;                  // 3125
    const int NBZ = (N_NODES + 255) / 256;                 // 196
    const int ZB = (N_NODES * 3 + 255) / 256;              // 587 (covers all init ranges)
    const int WARPB = (N_NODES * 32 + 255) / 256;          // 6250
    const int GEMMB = (N_NODES + 63) / 64;                 // 782

    zero_kernel<<<ZB, 256>>>();
    hist_kernel<<<EB, 256>>>(dst);
    scan1_kernel<<<NB_SCAN, 1024>>>();
    scan2_kernel<<<1, 64>>>(NB_SCAN);
    scan3_kernel<<<NBZ, 256>>>();
    scatter_kernel<<<EB, 256>>>(src, dst);

    k1_kernel<<<WARPB, 256>>>(feature, W1, al1, ar1);
    ws1_kernel<<<EB, 256>>>();
    agg1_kernel<<<WARPB, 256>>>();

    gemm2_kernel<<<GEMMB, 256>>>(W2, al2, ar2);
    ws2_kernel<<<EB, 256>>>();
    agg2_kernel<<<WARPB, 256>>>();

    pool_kernel<<<NBZ, 192>>>(gid);
    mlp_kernel<<<N_GRAPHS, 64>>>(gid, d1w, d1b, d2w, d2b, out);
}

// round 16
// speedup vs baseline: 1.2851x; 1.0996x over previous
#include <cuda_runtime.h>
#include <cuda_bf16.h>
#include <cstdint>

#define N_NODES 50000
#define N_EDGES 800000
#define N_GRAPHS 128

// ---------------- scratch (device globals; no allocations allowed) ----------------
__device__ float g_z1[N_NODES * 96];
__device__ float g_x1[N_NODES * 96];
__device__ float g_z2[N_NODES * 192];
__device__ float g_x2[N_NODES * 192];
__device__ float g_el1[N_NODES * 3];
__device__ float g_er1[N_NODES * 3];
__device__ float g_el2[N_NODES * 3];
__device__ float g_er2[N_NODES * 3];
__device__ int   g_deg[N_NODES];
__device__ int   g_off[N_NODES + 1];
__device__ int   g_cursor[N_NODES];
__device__ int   g_btot[64];
__device__ int   g_boff[64];
__device__ int   g_ssrc[N_EDGES];
__device__ float g_pool[N_GRAPHS * 192];

// ---------------- f32x2 packed-FMA helpers ----------------
__device__ __forceinline__ void fma_f32x2(unsigned long long& d, unsigned long long a,
                                          unsigned long long b) {
    asm("fma.rn.f32x2 %0, %1, %2, %0;" : "+l"(d) : "l"(a), "l"(b));
}
__device__ __forceinline__ unsigned long long pack_dup(float x) {
    unsigned long long r;
    asm("mov.b64 %0, {%1, %1};" : "=l"(r) : "f"(x));
    return r;
}
__device__ __forceinline__ float2 unpack_f32x2(unsigned long long v) {
    float2 r;
    asm("mov.b64 {%0, %1}, %2;" : "=f"(r.x), "=f"(r.y) : "l"(v));
    return r;
}

// ---------------- init ----------------
__global__ void zero_kernel() {
    int i = blockIdx.x * blockDim.x + threadIdx.x;
    if (i < N_NODES) g_deg[i] = 0;
    if (i < N_GRAPHS * 192) g_pool[i] = 0.f;
}

// ---------------- CSR build ----------------
__global__ void hist_kernel(const int* __restrict__ dst) {
    int e = blockIdx.x * blockDim.x + threadIdx.x;
    if (e < N_EDGES) atomicAdd(&g_deg[__ldg(dst + e)], 1);
}

__global__ void scan1_kernel() {
    __shared__ int sm[1024];
    int t = threadIdx.x;
    int i = blockIdx.x * 1024 + t;
    int v = (i < N_NODES) ? g_deg[i] : 0;
    sm[t] = v;
    __syncthreads();
#pragma unroll
    for (int o = 1; o < 1024; o <<= 1) {
        int x = (t >= o) ? sm[t - o] : 0;
        __syncthreads();
        sm[t] += x;
        __syncthreads();
    }
    if (i < N_NODES) g_off[i] = sm[t] - v;
    if (t == 1023) g_btot[blockIdx.x] = sm[1023];
}

__global__ void scan2_kernel(int nb) {
    __shared__ int sm[64];
    int t = threadIdx.x;
    int v = (t < nb) ? g_btot[t] : 0;
    sm[t] = v;
    __syncthreads();
#pragma unroll
    for (int o = 1; o < 64; o <<= 1) {
        int x = (t >= o) ? sm[t - o] : 0;
        __syncthreads();
        sm[t] += x;
        __syncthreads();
    }
    if (t < nb) g_boff[t] = sm[t] - v;
}

__global__ void scan3_kernel() {
    int i = blockIdx.x * blockDim.x + threadIdx.x;
    if (i < N_NODES) {
        int v = g_off[i] + g_boff[i >> 10];
        g_off[i] = v;
        g_cursor[i] = v;
    }
    if (i == 0) g_off[N_NODES] = N_EDGES;
}

__global__ void scatter_kernel(const int* __restrict__ src, const int* __restrict__ dst) {
    int e = blockIdx.x * blockDim.x + threadIdx.x;
    if (e < N_EDGES) {
        int d = __ldg(dst + e);
        int p = atomicAdd(&g_cursor[d], 1);
        g_ssrc[p] = __ldg(src + e);
    }
}

// ---------------- layer 1: z1 = feature @ W1 ; el1/er1 ----------------
__global__ void k1_kernel(const float* __restrict__ feat, const float* __restrict__ W1,
                          const float* __restrict__ al, const float* __restrict__ ar) {
    int warp = (blockIdx.x * blockDim.x + threadIdx.x) >> 5;
    if (warp >= N_NODES) return;
    int lane = threadIdx.x & 31;
    float f[10];
#pragma unroll
    for (int k = 0; k < 10; k++) f[k] = __ldg(feat + warp * 10 + k);
    float el[3], er[3];
#pragma unroll
    for (int h = 0; h < 3; h++) {
        int c = h * 32 + lane;
        float z = 0.f;
#pragma unroll
        for (int k = 0; k < 10; k++) z += f[k] * __ldg(W1 + k * 96 + c);
        g_z1[warp * 96 + c] = z;
        el[h] = z * __ldg(al + c);
        er[h] = z * __ldg(ar + c);
    }
#pragma unroll
    for (int o = 16; o; o >>= 1) {
#pragma unroll
        for (int h = 0; h < 3; h++) {
            el[h] += __shfl_xor_sync(0xffffffffu, el[h], o);
            er[h] += __shfl_xor_sync(0xffffffffu, er[h], o);
        }
    }
    if (lane == 0) {
#pragma unroll
        for (int h = 0; h < 3; h++) {
            g_el1[warp * 3 + h] = el[h];
            g_er1[warp * 3 + h] = er[h];
        }
    }
}

// ---------------- aggregation (softmax weights computed inline) ----------------
// Softmax is shift-invariant; logits are O(10) max, far from expf overflow, so the
// reference's max-subtraction is dropped. Each lane recomputes w for its head and
// accumulates the denominator s in registers -> no edge-parallel ws pass, no atomics.
__global__ void agg1_kernel() {
    int node = (blockIdx.x * blockDim.x + threadIdx.x) >> 5;
    if (node >= N_NODES) return;
    int lane = threadIdx.x & 31;
    bool act = lane < 24;                 // 24 float4 = 96 floats
    int q = act ? lane : 23;
    int h = q >> 3;                       // head = float4 idx / 8
    float er_h = g_er1[node * 3 + h];
    float4 a = make_float4(0.f, 0.f, 0.f, 0.f);
    float s = 0.f;
    int beg = g_off[node], end = g_off[node + 1];
    const float4* z4 = (const float4*)g_z1;
    int p = beg;
    for (; p + 2 <= end; p += 2) {        // unroll-by-2: independent gathers
        int sn0 = g_ssrc[p], sn1 = g_ssrc[p + 1];
        float el0 = __ldg(&g_el1[sn0 * 3 + h]);
        float el1v = __ldg(&g_el1[sn1 * 3 + h]);
        float4 v0 = __ldg(&z4[(size_t)sn0 * 24 + q]);
        float4 v1 = __ldg(&z4[(size_t)sn1 * 24 + q]);
        float e0 = el0 + er_h; e0 = e0 > 0.f ? e0 : 0.2f * e0;
        float e1 = el1v + er_h; e1 = e1 > 0.f ? e1 : 0.2f * e1;
        float w0 = __expf(e0), w1 = __expf(e1);
        if (!act) { w0 = 0.f; w1 = 0.f; }
        s += w0 + w1;
        a.x += w0 * v0.x + w1 * v1.x;
        a.y += w0 * v0.y + w1 * v1.y;
        a.z += w0 * v0.z + w1 * v1.z;
        a.w += w0 * v0.w + w1 * v1.w;
    }
    if (p < end) {
        int sn0 = g_ssrc[p];
        float el0 = __ldg(&g_el1[sn0 * 3 + h]);
        float4 v0 = __ldg(&z4[(size_t)sn0 * 24 + q]);
        float e0 = el0 + er_h; e0 = e0 > 0.f ? e0 : 0.2f * e0;
        float w0 = __expf(e0);
        if (!act) w0 = 0.f;
        s += w0;
        a.x += w0 * v0.x; a.y += w0 * v0.y; a.z += w0 * v0.z; a.w += w0 * v0.w;
    }
    if (act) {
        float inv = 1.f / (s + 1e-16f);
        float4 r;
        r.x = fmaxf(a.x * inv, 0.f); r.y = fmaxf(a.y * inv, 0.f);
        r.z = fmaxf(a.z * inv, 0.f); r.w = fmaxf(a.w * inv, 0.f);
        ((float4*)g_x1)[(size_t)node * 24 + q] = r;
    }
}

__global__ void agg2_kernel() {
    int node = (blockIdx.x * blockDim.x + threadIdx.x) >> 5;
    if (node >= N_NODES) return;
    int lane = threadIdx.x & 31;
    int h0 = lane >> 4;                   // head for first float4 (0 or 1)
    int q1 = 32 + (lane & 15);            // second float4 index (head 2)
    bool act2 = lane < 16;
    float er0 = g_er2[node * 3 + h0];
    float er2v = g_er2[node * 3 + 2];
    float4 a0 = make_float4(0.f, 0.f, 0.f, 0.f);
    float4 a1 = make_float4(0.f, 0.f, 0.f, 0.f);
    float s0 = 0.f, s2 = 0.f;
    int beg = g_off[node], end = g_off[node + 1];
    const float4* z4 = (const float4*)g_z2;
    int p = beg;
    for (; p + 2 <= end; p += 2) {        // unroll-by-2
        int sn0 = g_ssrc[p], sn1 = g_ssrc[p + 1];
        float elA0 = __ldg(&g_el2[sn0 * 3 + h0]);
        float elA2 = __ldg(&g_el2[sn0 * 3 + 2]);
        float elB0 = __ldg(&g_el2[sn1 * 3 + h0]);
        float elB2 = __ldg(&g_el2[sn1 * 3 + 2]);
        const float4* zpA = z4 + (size_t)sn0 * 48;
        const float4* zpB = z4 + (size_t)sn1 * 48;
        float4 vA0 = __ldg(zpA + lane);
        float4 vA1 = __ldg(zpA + q1);
        float4 vB0 = __ldg(zpB + lane);
        float4 vB1 = __ldg(zpB + q1);
        float eA0 = elA0 + er0;  eA0 = eA0 > 0.f ? eA0 : 0.2f * eA0;
        float eA2 = elA2 + er2v; eA2 = eA2 > 0.f ? eA2 : 0.2f * eA2;
        float eB0 = elB0 + er0;  eB0 = eB0 > 0.f ? eB0 : 0.2f * eB0;
        float eB2 = elB2 + er2v; eB2 = eB2 > 0.f ? eB2 : 0.2f * eB2;
        float wA0 = __expf(eA0), wA2 = __expf(eA2);
        float wB0 = __expf(eB0), wB2 = __expf(eB2);
        if (!act2) { wA2 = 0.f; wB2 = 0.f; }
        s0 += wA0 + wB0;
        s2 += wA2 + wB2;
        a0.x += wA0 * vA0.x + wB0 * vB0.x;
        a0.y += wA0 * vA0.y + wB0 * vB0.y;
        a0.z += wA0 * vA0.z + wB0 * vB0.z;
        a0.w += wA0 * vA0.w + wB0 * vB0.w;
        a1.x += wA2 * vA1.x + wB2 * vB1.x;
        a1.y += wA2 * vA1.y + wB2 * vB1.y;
        a1.z += wA2 * vA1.z + wB2 * vB1.z;
        a1.w += wA2 * vA1.w + wB2 * vB1.w;
    }
    if (p < end) {
        int sn0 = g_ssrc[p];
        float elA0 = __ldg(&g_el2[sn0 * 3 + h0]);
        float elA2 = __ldg(&g_el2[sn0 * 3 + 2]);
        const float4* zpA = z4 + (size_t)sn0 * 48;
        float4 vA0 = __ldg(zpA + lane);
        float4 vA1 = __ldg(zpA + q1);
        float eA0 = elA0 + er0;  eA0 = eA0 > 0.f ? eA0 : 0.2f * eA0;
        float eA2 = elA2 + er2v; eA2 = eA2 > 0.f ? eA2 : 0.2f * eA2;
        float wA0 = __expf(eA0), wA2 = __expf(eA2);
        if (!act2) wA2 = 0.f;
        s0 += wA0; s2 += wA2;
        a0.x += wA0 * vA0.x; a0.y += wA0 * vA0.y;
        a0.z += wA0 * vA0.z; a0.w += wA0 * vA0.w;
        a1.x += wA2 * vA1.x; a1.y += wA2 * vA1.y;
        a1.z += wA2 * vA1.z; a1.w += wA2 * vA1.w;
    }
    float inv0 = 1.f / (s0 + 1e-16f);
    float inv2 = 1.f / (s2 + 1e-16f);
    float4* xo = (float4*)g_x2 + (size_t)node * 48;
    float4 r0;
    r0.x = fmaxf(a0.x * inv0, 0.f); r0.y = fmaxf(a0.y * inv0, 0.f);
    r0.z = fmaxf(a0.z * inv0, 0.f); r0.w = fmaxf(a0.w * inv0, 0.f);
    xo[lane] = r0;
    if (act2) {
        float4 r1;
        r1.x = fmaxf(a1.x * inv2, 0.f); r1.y = fmaxf(a1.y * inv2, 0.f);
        r1.z = fmaxf(a1.z * inv2, 0.f); r1.w = fmaxf(a1.w * inv2, 0.f);
        xo[q1] = r1;
    }
}

// ---------------- layer 2 GEMM (f32x2 packed FMA) + fused el2/er2 epilogue --------
__global__ __launch_bounds__(256) void gemm2_kernel(const float* __restrict__ W2,
                                                    const float* __restrict__ al2,
                                                    const float* __restrict__ ar2) {
    __shared__ float xs[32][65];
    __shared__ float ws[32][192];
    int tid = threadIdx.x;
    int tx = tid & 15, ty = tid >> 4;
    int n0 = blockIdx.x * 64;
    unsigned long long acc2[4][6];
#pragma unroll
    for (int i = 0; i < 4; i++)
#pragma unroll
        for (int j = 0; j < 6; j++) acc2[i][j] = 0ull;

    for (int kt = 0; kt < 3; kt++) {
#pragma unroll
        for (int r = 0; r < 8; r++) {
            int idx = r * 256 + tid;
            int m = idx >> 5, k = idx & 31;
            int node = n0 + m;
            xs[k][m] = (node < N_NODES) ? g_x1[(size_t)node * 96 + kt * 32 + k] : 0.f;
        }
#pragma unroll
        for (int r = 0; r < 24; r++) {
            int idx = r * 256 + tid;
            int k = idx / 192, c = idx % 192;
            ws[k][c] = __ldg(W2 + (kt * 32 + k) * 192 + c);
        }
        __syncthreads();
#pragma unroll
        for (int k = 0; k < 32; k++) {
            unsigned long long ap[4];
#pragma unroll
            for (int i = 0; i < 4; i++) ap[i] = pack_dup(xs[k][ty * 4 + i]);
            // b pairs: ws[k][tx*12 + 2j, 2j+1] -- 8B-aligned, read as 64-bit LDS
            const unsigned long long* bw =
                reinterpret_cast<const unsigned long long*>(&ws[k][tx * 12]);
            unsigned long long bp[6];
#pragma unroll
            for (int j = 0; j < 6; j++) bp[j] = bw[j];
#pragma unroll
            for (int i = 0; i < 4; i++)
#pragma unroll
                for (int j = 0; j < 6; j++) fma_f32x2(acc2[i][j], ap[i], bp[j]);
        }
        __syncthreads();
    }
#pragma unroll
    for (int i = 0; i < 4; i++) {
        float acc[12];
#pragma unroll
        for (int j = 0; j < 6; j++) {
            float2 u = unpack_f32x2(acc2[i][j]);
            acc[2 * j] = u.x;
            acc[2 * j + 1] = u.y;
        }
        int node = n0 + ty * 4 + i;
        if (node < N_NODES) {
#pragma unroll
            for (int j = 0; j < 12; j++)
                g_z2[(size_t)node * 192 + tx * 12 + j] = acc[j];
        }
        // fused el2/er2: per-thread partials over 12 cols, 16-lane shfl reduce
        float elp[3] = {0.f, 0.f, 0.f}, erp[3] = {0.f, 0.f, 0.f};
#pragma unroll
        for (int j = 0; j < 12; j++) {
            int col = tx * 12 + j;
            int h = col >> 6;
            float v = acc[j];
            elp[h] += v * __ldg(al2 + col);
            erp[h] += v * __ldg(ar2 + col);
        }
#pragma unroll
        for (int o = 1; o < 16; o <<= 1) {
#pragma unroll
            for (int h = 0; h < 3; h++) {
                elp[h] += __shfl_xor_sync(0xffffffffu, elp[h], o);
                erp[h] += __shfl_xor_sync(0xffffffffu, erp[h], o);
            }
        }
        if (tx == 0 && node < N_NODES) {
#pragma unroll
            for (int h = 0; h < 3; h++) {
                g_el2[node * 3 + h] = elp[h];
                g_er2[node * 3 + h] = erp[h];
            }
        }
    }
}

// ---------------- pooling: graph_ids sorted -> run-length local sums ----------------
__global__ void pool_kernel(const int* __restrict__ gid) {
    int c = threadIdx.x;   // 192 threads
    int n0 = blockIdx.x * 256;
    int nend = n0 + 256;
    if (nend > N_NODES) nend = N_NODES;
    if (n0 >= N_NODES) return;
    int curg = __ldg(gid + n0);
    float a = 0.f;
    for (int n = n0; n < nend; n++) {
        int g = __ldg(gid + n);
        if (g != curg) {
            atomicAdd(&g_pool[curg * 192 + c], a);
            a = 0.f;
            curg = g;
        }
        a += g_x2[(size_t)n * 192 + c];
    }
    atomicAdd(&g_pool[curg * 192 + c], a);
}

// ---------------- MLP head: one block per graph ----------------
__global__ void mlp_kernel(const int* __restrict__ gid, const float* __restrict__ d1w,
                           const float* __restrict__ d1b, const float* __restrict__ d2w,
                           const float* __restrict__ d2b, float* __restrict__ out) {
    int g = blockIdx.x;
    int t = threadIdx.x;   // 64
    __shared__ float red[2];
    __shared__ float s_inv;
    if (t == 0) {
        int lo = 0, hi = N_NODES;
        while (lo < hi) { int mid = (lo + hi) >> 1; if (__ldg(gid + mid) < g) lo = mid + 1; else hi = mid; }
        int lb = lo;
        lo = 0; hi = N_NODES;
        while (lo < hi) { int mid = (lo + hi) >> 1; if (__ldg(gid + mid) < g + 1) lo = mid + 1; else hi = mid; }
        float cnt = (float)(lo - lb);
        s_inv = 1.f / fmaxf(cnt, 1.f);
    }
    __syncthreads();
    float inv = s_inv;
    float dot = 0.f;
#pragma unroll 4
    for (int k = 0; k < 192; k++)
        dot += g_pool[g * 192 + k] * __ldg(d1w + k * 64 + t);
    float h = __ldg(d1b + t) + inv * dot;
    h = fmaxf(h, 0.f);
    float v = h * __ldg(d2w + t);
#pragma unroll
    for (int o = 16; o; o >>= 1) v += __shfl_xor_sync(0xffffffffu, v, o);
    if ((t & 31) == 0) red[t >> 5] = v;
    __syncthreads();
    if (t == 0) out[g] = red[0] + red[1] + __ldg(d2b);
}

// ---------------- launch ----------------
extern "C" void kernel_launch(void* const* d_in, const int* in_sizes, int n_in,
                              void* d_out, int out_size) {
    const float* feature = (const float*)d_in[0];
    const int*   src     = (const int*)d_in[1];
    const int*   dst     = (const int*)d_in[2];
    const int*   gid     = (const int*)d_in[3];
    const float* W1      = (const float*)d_in[4];
    const float* al1     = (const float*)d_in[5];
    const float* ar1     = (const float*)d_in[6];
    const float* W2      = (const float*)d_in[7];
    const float* al2     = (const float*)d_in[8];
    const float* ar2     = (const float*)d_in[9];
    const float* d1w     = (const float*)d_in[10];
    const float* d1b     = (const float*)d_in[11];
    const float* d2w     = (const float*)d_in[12];
    const float* d2b     = (const float*)d_in[13];
    float* out = (float*)d_out;

    const int NB_SCAN = (N_NODES + 1023) / 1024;           // 49
    const int EB = (N_EDGES + 255) / 256;                  // 3125
    const int NBZ = (N_NODES + 255) / 256;                 // 196
    const int WARPB = (N_NODES * 32 + 255) / 256;          // 6250
    const int GEMMB = (N_NODES + 63) / 64;                 // 782

    zero_kernel<<<NBZ, 256>>>();
    hist_kernel<<<EB, 256>>>(dst);
    scan1_kernel<<<NB_SCAN, 1024>>>();
    scan2_kernel<<<1, 64>>>(NB_SCAN);
    scan3_kernel<<<NBZ, 256>>>();
    scatter_kernel<<<EB, 256>>>(src, dst);

    k1_kernel<<<WARPB, 256>>>(feature, W1, al1, ar1);
    agg1_kernel<<<WARPB, 256>>>();

    gemm2_kernel<<<GEMMB, 256>>>(W2, al2, ar2);
    agg2_kernel<<<WARPB, 256>>>();

    pool_kernel<<<NBZ, 192>>>(gid);
    mlp_kernel<<<N_GRAPHS, 64>>>(gid, d1w, d1b, d2w, d2b, out);
}